// round 1
// baseline (speedup 1.0000x reference)
#include <cuda_runtime.h>
#include <stdint.h>

// Scratch for the global min/max reduction, stored as order-preserving
// unsigned ints so we can use atomicMin/atomicMax.
__device__ unsigned int g_min_bits;  // init 0xFFFFFFFF
__device__ unsigned int g_max_bits;  // init 0x00000000

// Order-preserving float <-> uint mapping:
// flip: negative floats -> ~bits (descending negatives become ascending),
//       non-negative    -> bits | sign bit.
__device__ __forceinline__ unsigned int flip_f2u(float f) {
    unsigned int b = __float_as_uint(f);
    return (b & 0x80000000u) ? ~b : (b | 0x80000000u);
}
__device__ __forceinline__ float unflip_u2f(unsigned int b) {
    unsigned int r = (b & 0x80000000u) ? (b & 0x7FFFFFFFu) : ~b;
    return __uint_as_float(r);
}

__global__ void init_minmax_kernel() {
    g_min_bits = 0xFFFFFFFFu;
    g_max_bits = 0x00000000u;
}

__global__ void __launch_bounds__(256) minmax_reduce_kernel(
    const float4* __restrict__ x4, int n4) {
    float mn = 3.402823466e+38f;   //  FLT_MAX
    float mx = -3.402823466e+38f;  // -FLT_MAX

    int stride = gridDim.x * blockDim.x;
    for (int i = blockIdx.x * blockDim.x + threadIdx.x; i < n4; i += stride) {
        float4 v = x4[i];
        mn = fminf(mn, fminf(fminf(v.x, v.y), fminf(v.z, v.w)));
        mx = fmaxf(mx, fmaxf(fmaxf(v.x, v.y), fmaxf(v.z, v.w)));
    }

    // Warp reduce
    #pragma unroll
    for (int off = 16; off > 0; off >>= 1) {
        mn = fminf(mn, __shfl_xor_sync(0xFFFFFFFFu, mn, off));
        mx = fmaxf(mx, __shfl_xor_sync(0xFFFFFFFFu, mx, off));
    }

    // Block reduce via shared memory (8 warps @ 256 threads)
    __shared__ float s_mn[8];
    __shared__ float s_mx[8];
    int wid = threadIdx.x >> 5;
    int lid = threadIdx.x & 31;
    if (lid == 0) { s_mn[wid] = mn; s_mx[wid] = mx; }
    __syncthreads();
    if (wid == 0) {
        int nw = blockDim.x >> 5;
        mn = (lid < nw) ? s_mn[lid] : 3.402823466e+38f;
        mx = (lid < nw) ? s_mx[lid] : -3.402823466e+38f;
        #pragma unroll
        for (int off = 4; off > 0; off >>= 1) {
            mn = fminf(mn, __shfl_xor_sync(0xFFFFFFFFu, mn, off));
            mx = fmaxf(mx, __shfl_xor_sync(0xFFFFFFFFu, mx, off));
        }
        if (lid == 0) {
            atomicMin(&g_min_bits, flip_f2u(mn));
            atomicMax(&g_max_bits, flip_f2u(mx));
        }
    }
}

// out = rint((x - mn) * scale) / scale + mn, scale = 255 / (mx - mn).
// clip(x, min(x), max(x)) == x, so the clip is dropped.
__global__ void __launch_bounds__(256) fakequant_apply_kernel(
    const float4* __restrict__ x4, float4* __restrict__ out4, int n4) {
    int i = blockIdx.x * blockDim.x + threadIdx.x;
    if (i >= n4) return;

    float mn = unflip_u2f(g_min_bits);
    float mx = unflip_u2f(g_max_bits);
    float scale = 255.0f / (mx - mn);
    float inv_scale = 1.0f / scale;  // one division per thread, amortized over 4 elems

    float4 v = x4[i];
    float4 r;
    r.x = fmaf(rintf((v.x - mn) * scale), inv_scale, mn);
    r.y = fmaf(rintf((v.y - mn) * scale), inv_scale, mn);
    r.z = fmaf(rintf((v.z - mn) * scale), inv_scale, mn);
    r.w = fmaf(rintf((v.w - mn) * scale), inv_scale, mn);
    out4[i] = r;
}

// Scalar tail (n not divisible by 4 — not hit for this shape, kept for safety)
__global__ void fakequant_tail_kernel(const float* __restrict__ x,
                                      float* __restrict__ out,
                                      int start, int n) {
    int i = start + blockIdx.x * blockDim.x + threadIdx.x;
    if (i >= n) return;
    float mn = unflip_u2f(g_min_bits);
    float mx = unflip_u2f(g_max_bits);
    float scale = 255.0f / (mx - mn);
    float inv_scale = 1.0f / scale;
    out[i] = fmaf(rintf((x[i] - mn) * scale), inv_scale, mn);
}

extern "C" void kernel_launch(void* const* d_in, const int* in_sizes, int n_in,
                              void* d_out, int out_size) {
    const float* x = (const float*)d_in[0];
    float* out = (float*)d_out;
    int n = in_sizes[0];
    int n4 = n >> 2;
    int tail_start = n4 << 2;

    init_minmax_kernel<<<1, 1>>>();

    // Reduce: 8 blocks per SM (148 SMs) x 256 threads, grid-stride float4.
    int red_blocks = 148 * 8;
    minmax_reduce_kernel<<<red_blocks, 256>>>((const float4*)x, n4);

    // Apply: one float4 per thread.
    int app_blocks = (n4 + 255) / 256;
    fakequant_apply_kernel<<<app_blocks, 256>>>((const float4*)x, (float4*)out, n4);

    if (tail_start < n) {
        int tail = n - tail_start;
        fakequant_tail_kernel<<<(tail + 255) / 256, 256>>>(x, out, tail_start, n);
    }
}

// round 2
// speedup vs baseline: 1.0906x; 1.0906x over previous
#include <cuda_runtime.h>
#include <stdint.h>

// ---------------------------------------------------------------------------
// FakeQuant with global min/max:
//   mn = min(x), mx = max(x), scale = 255/(mx-mn)
//   out = rint((x - mn)*scale)/scale + mn        (clip(x,mn,mx)==x, dropped)
//
// 2 launches, no init kernel:
//   1) minmax_reduce:  per-block partial (min,max) -> g_partials[block]
//                      (plain stores, nothing needs pre-initialization)
//   2) fakequant_apply: each block reduces the partials in a parallel
//                      prologue, then applies the quant in a HIGH->LOW sweep
//                      so the x-tail left in L2 by the reduce pass is reused.
// ---------------------------------------------------------------------------

#define RED_BLOCKS (148 * 8)   // 1184 reduce blocks
#define TPB 256

__device__ float2 g_partials[RED_BLOCKS];  // .x = min, .y = max

// ---------------- reduce: forward sweep, default (allocating) loads --------
__global__ void __launch_bounds__(TPB) minmax_reduce_kernel(
    const float4* __restrict__ x4, int n4) {
    float mn = 3.402823466e+38f;
    float mx = -3.402823466e+38f;

    const int S = gridDim.x * blockDim.x;
    int i = blockIdx.x * blockDim.x + threadIdx.x;

    // Unrolled x4 for MLP: 4 outstanding float4 loads per thread.
    for (; i + 3 * S < n4; i += 4 * S) {
        float4 a = x4[i];
        float4 b = x4[i + S];
        float4 c = x4[i + 2 * S];
        float4 d = x4[i + 3 * S];
        mn = fminf(mn, fminf(fminf(a.x, a.y), fminf(a.z, a.w)));
        mx = fmaxf(mx, fmaxf(fmaxf(a.x, a.y), fmaxf(a.z, a.w)));
        mn = fminf(mn, fminf(fminf(b.x, b.y), fminf(b.z, b.w)));
        mx = fmaxf(mx, fmaxf(fmaxf(b.x, b.y), fmaxf(b.z, b.w)));
        mn = fminf(mn, fminf(fminf(c.x, c.y), fminf(c.z, c.w)));
        mx = fmaxf(mx, fmaxf(fmaxf(c.x, c.y), fmaxf(c.z, c.w)));
        mn = fminf(mn, fminf(fminf(d.x, d.y), fminf(d.z, d.w)));
        mx = fmaxf(mx, fmaxf(fmaxf(d.x, d.y), fmaxf(d.z, d.w)));
    }
    for (; i < n4; i += S) {
        float4 a = x4[i];
        mn = fminf(mn, fminf(fminf(a.x, a.y), fminf(a.z, a.w)));
        mx = fmaxf(mx, fmaxf(fmaxf(a.x, a.y), fmaxf(a.z, a.w)));
    }

    // warp reduce
    #pragma unroll
    for (int off = 16; off > 0; off >>= 1) {
        mn = fminf(mn, __shfl_xor_sync(0xFFFFFFFFu, mn, off));
        mx = fmaxf(mx, __shfl_xor_sync(0xFFFFFFFFu, mx, off));
    }
    // block reduce
    __shared__ float s_mn[TPB / 32];
    __shared__ float s_mx[TPB / 32];
    int wid = threadIdx.x >> 5;
    int lid = threadIdx.x & 31;
    if (lid == 0) { s_mn[wid] = mn; s_mx[wid] = mx; }
    __syncthreads();
    if (wid == 0) {
        const int nw = TPB / 32;
        mn = (lid < nw) ? s_mn[lid] : 3.402823466e+38f;
        mx = (lid < nw) ? s_mx[lid] : -3.402823466e+38f;
        #pragma unroll
        for (int off = 4; off > 0; off >>= 1) {
            mn = fminf(mn, __shfl_xor_sync(0xFFFFFFFFu, mn, off));
            mx = fmaxf(mx, __shfl_xor_sync(0xFFFFFFFFu, mx, off));
        }
        if (lid == 0) g_partials[blockIdx.x] = make_float2(mn, mx);
    }
}

// Parallel prologue: reduce g_partials within a block, broadcast via smem.
__device__ __forceinline__ void reduce_partials_block(float& out_mn, float& out_mx) {
    float mn = 3.402823466e+38f;
    float mx = -3.402823466e+38f;
    for (int p = threadIdx.x; p < RED_BLOCKS; p += blockDim.x) {
        float2 v = g_partials[p];
        mn = fminf(mn, v.x);
        mx = fmaxf(mx, v.y);
    }
    #pragma unroll
    for (int off = 16; off > 0; off >>= 1) {
        mn = fminf(mn, __shfl_xor_sync(0xFFFFFFFFu, mn, off));
        mx = fmaxf(mx, __shfl_xor_sync(0xFFFFFFFFu, mx, off));
    }
    __shared__ float s_mn[TPB / 32];
    __shared__ float s_mx[TPB / 32];
    int wid = threadIdx.x >> 5;
    int lid = threadIdx.x & 31;
    if (lid == 0) { s_mn[wid] = mn; s_mx[wid] = mx; }
    __syncthreads();
    __shared__ float s_fmn, s_fmx;
    if (wid == 0) {
        const int nw = TPB / 32;
        mn = (lid < nw) ? s_mn[lid] : 3.402823466e+38f;
        mx = (lid < nw) ? s_mx[lid] : -3.402823466e+38f;
        #pragma unroll
        for (int off = 4; off > 0; off >>= 1) {
            mn = fminf(mn, __shfl_xor_sync(0xFFFFFFFFu, mn, off));
            mx = fmaxf(mx, __shfl_xor_sync(0xFFFFFFFFu, mx, off));
        }
        if (lid == 0) { s_fmn = mn; s_fmx = mx; }
    }
    __syncthreads();
    out_mn = s_fmn;
    out_mx = s_fmx;
}

__device__ __forceinline__ float4 fq4(float4 v, float mn, float scale, float inv) {
    float4 r;
    r.x = fmaf(rintf((v.x - mn) * scale), inv, mn);
    r.y = fmaf(rintf((v.y - mn) * scale), inv, mn);
    r.z = fmaf(rintf((v.z - mn) * scale), inv, mn);
    r.w = fmaf(rintf((v.w - mn) * scale), inv, mn);
    return r;
}

// ---------------- apply: HIGH->LOW sweep to reuse the L2-resident x tail ---
__global__ void __launch_bounds__(TPB) fakequant_apply_kernel(
    const float4* __restrict__ x4, float4* __restrict__ out4, int n4) {
    float mn, mx;
    reduce_partials_block(mn, mx);
    const float scale = 255.0f / (mx - mn);
    const float inv   = 1.0f / scale;

    const int S = gridDim.x * blockDim.x;
    const int gtid = blockIdx.x * blockDim.x + threadIdx.x;
    if (gtid >= n4) return;

    int k = (n4 - 1 - gtid) / S;  // highest valid stride index for this thread

    // Descending sweep, unrolled x4 for MLP.
    for (; k >= 3; k -= 4) {
        int i0 = gtid + k * S;
        int i1 = i0 - S;
        int i2 = i0 - 2 * S;
        int i3 = i0 - 3 * S;
        float4 a = x4[i0];
        float4 b = x4[i1];
        float4 c = x4[i2];
        float4 d = x4[i3];
        __stcs(&out4[i0], fq4(a, mn, scale, inv));
        __stcs(&out4[i1], fq4(b, mn, scale, inv));
        __stcs(&out4[i2], fq4(c, mn, scale, inv));
        __stcs(&out4[i3], fq4(d, mn, scale, inv));
    }
    for (; k >= 0; --k) {
        int i0 = gtid + k * S;
        __stcs(&out4[i0], fq4(x4[i0], mn, scale, inv));
    }
}

// Scalar tail (never hit for this shape: n % 1024 == 0; kept for generality).
__global__ void fakequant_tail_kernel(const float* __restrict__ x,
                                      float* __restrict__ out,
                                      int start, int n) {
    float mn = 3.402823466e+38f;
    float mx = -3.402823466e+38f;
    for (int p = 0; p < RED_BLOCKS; ++p) {
        float2 v = g_partials[p];
        mn = fminf(mn, v.x);
        mx = fmaxf(mx, v.y);
    }
    const float scale = 255.0f / (mx - mn);
    const float inv   = 1.0f / scale;
    int i = start + blockIdx.x * blockDim.x + threadIdx.x;
    if (i < n) out[i] = fmaf(rintf((x[i] - mn) * scale), inv, mn);
}

extern "C" void kernel_launch(void* const* d_in, const int* in_sizes, int n_in,
                              void* d_out, int out_size) {
    const float* x = (const float*)d_in[0];
    float* out = (float*)d_out;
    int n = in_sizes[0];
    int n4 = n >> 2;
    int tail_start = n4 << 2;

    minmax_reduce_kernel<<<RED_BLOCKS, TPB>>>((const float4*)x, n4);
    fakequant_apply_kernel<<<RED_BLOCKS, TPB>>>((const float4*)x, (float4*)out, n4);

    if (tail_start < n) {
        int tail = n - tail_start;
        fakequant_tail_kernel<<<(tail + TPB - 1) / TPB, TPB>>>(x, out, tail_start, n);
    }
}

// round 3
// speedup vs baseline: 1.0988x; 1.0075x over previous
#include <cuda_runtime.h>
#include <stdint.h>

// ---------------------------------------------------------------------------
// FakeQuant with global min/max:
//   mn = min(x), mx = max(x), scale = 255/(mx-mn)
//   out = rint((x - mn)*scale)/scale + mn        (clip(x,mn,mx)==x, dropped)
//
// L2-reuse scheme:
//   reduce sweeps low->high; reads below `keep_thresh` are __ldcs
//   (evict-first) so the LAST ~112MB of x stays L2-resident (evict-normal).
//   apply sweeps high->low consuming that resident tail first; its own reads
//   are __ldcs and writes __stcs so neither stream churns the tail out.
// ---------------------------------------------------------------------------

#define RED_BLOCKS (148 * 8)   // 1184 blocks = one full wave at 8 blocks/SM
#define TPB 256

__device__ float2 g_partials[RED_BLOCKS];  // .x = min, .y = max

// ---------------- reduce: forward sweep -------------------------------------
__global__ void __launch_bounds__(TPB) minmax_reduce_kernel(
    const float4* __restrict__ x4, int n4, int keep_thresh) {
    float mn = 3.402823466e+38f;
    float mx = -3.402823466e+38f;

    const int S = gridDim.x * blockDim.x;
    int i = blockIdx.x * blockDim.x + threadIdx.x;

    #define ACC4(v)                                               \
        mn = fminf(mn, fminf(fminf((v).x, (v).y), fminf((v).z, (v).w))); \
        mx = fmaxf(mx, fmaxf(fmaxf((v).x, (v).y), fmaxf((v).z, (v).w)))

    // Early region: evict-first loads (never reused, don't pollute L2).
    for (; i + 3 * S < keep_thresh; i += 4 * S) {
        float4 a = __ldcs(&x4[i]);
        float4 b = __ldcs(&x4[i + S]);
        float4 c = __ldcs(&x4[i + 2 * S]);
        float4 d = __ldcs(&x4[i + 3 * S]);
        ACC4(a); ACC4(b); ACC4(c); ACC4(d);
    }
    for (; i < keep_thresh; i += S) {
        float4 a = __ldcs(&x4[i]);
        ACC4(a);
    }
    // Tail region: default (evict-normal) loads — these stay in L2 for apply.
    for (; i + 3 * S < n4; i += 4 * S) {
        float4 a = x4[i];
        float4 b = x4[i + S];
        float4 c = x4[i + 2 * S];
        float4 d = x4[i + 3 * S];
        ACC4(a); ACC4(b); ACC4(c); ACC4(d);
    }
    for (; i < n4; i += S) {
        float4 a = x4[i];
        ACC4(a);
    }
    #undef ACC4

    // warp reduce
    #pragma unroll
    for (int off = 16; off > 0; off >>= 1) {
        mn = fminf(mn, __shfl_xor_sync(0xFFFFFFFFu, mn, off));
        mx = fmaxf(mx, __shfl_xor_sync(0xFFFFFFFFu, mx, off));
    }
    // block reduce
    __shared__ float s_mn[TPB / 32];
    __shared__ float s_mx[TPB / 32];
    int wid = threadIdx.x >> 5;
    int lid = threadIdx.x & 31;
    if (lid == 0) { s_mn[wid] = mn; s_mx[wid] = mx; }
    __syncthreads();
    if (wid == 0) {
        const int nw = TPB / 32;
        mn = (lid < nw) ? s_mn[lid] : 3.402823466e+38f;
        mx = (lid < nw) ? s_mx[lid] : -3.402823466e+38f;
        #pragma unroll
        for (int off = 4; off > 0; off >>= 1) {
            mn = fminf(mn, __shfl_xor_sync(0xFFFFFFFFu, mn, off));
            mx = fmaxf(mx, __shfl_xor_sync(0xFFFFFFFFu, mx, off));
        }
        if (lid == 0) g_partials[blockIdx.x] = make_float2(mn, mx);
    }
}

// Parallel prologue: reduce g_partials within a block, broadcast via smem.
__device__ __forceinline__ void reduce_partials_block(float& out_mn, float& out_mx) {
    float mn = 3.402823466e+38f;
    float mx = -3.402823466e+38f;
    for (int p = threadIdx.x; p < RED_BLOCKS; p += blockDim.x) {
        float2 v = g_partials[p];
        mn = fminf(mn, v.x);
        mx = fmaxf(mx, v.y);
    }
    #pragma unroll
    for (int off = 16; off > 0; off >>= 1) {
        mn = fminf(mn, __shfl_xor_sync(0xFFFFFFFFu, mn, off));
        mx = fmaxf(mx, __shfl_xor_sync(0xFFFFFFFFu, mx, off));
    }
    __shared__ float s_mn[TPB / 32];
    __shared__ float s_mx[TPB / 32];
    int wid = threadIdx.x >> 5;
    int lid = threadIdx.x & 31;
    if (lid == 0) { s_mn[wid] = mn; s_mx[wid] = mx; }
    __syncthreads();
    __shared__ float s_fmn, s_fmx;
    if (wid == 0) {
        const int nw = TPB / 32;
        mn = (lid < nw) ? s_mn[lid] : 3.402823466e+38f;
        mx = (lid < nw) ? s_mx[lid] : -3.402823466e+38f;
        #pragma unroll
        for (int off = 4; off > 0; off >>= 1) {
            mn = fminf(mn, __shfl_xor_sync(0xFFFFFFFFu, mn, off));
            mx = fmaxf(mx, __shfl_xor_sync(0xFFFFFFFFu, mx, off));
        }
        if (lid == 0) { s_fmn = mn; s_fmx = mx; }
    }
    __syncthreads();
    out_mn = s_fmn;
    out_mx = s_fmx;
}

__device__ __forceinline__ float4 fq4(float4 v, float mn, float scale, float inv) {
    float4 r;
    r.x = fmaf(rintf((v.x - mn) * scale), inv, mn);
    r.y = fmaf(rintf((v.y - mn) * scale), inv, mn);
    r.z = fmaf(rintf((v.z - mn) * scale), inv, mn);
    r.w = fmaf(rintf((v.w - mn) * scale), inv, mn);
    return r;
}

// ---------------- apply: high->low sweep, streaming reads + writes ----------
__global__ void __launch_bounds__(TPB) fakequant_apply_kernel(
    const float4* __restrict__ x4, float4* __restrict__ out4, int n4) {
    float mn, mx;
    reduce_partials_block(mn, mx);
    const float scale = 255.0f / (mx - mn);
    const float inv   = 1.0f / scale;

    const int S = gridDim.x * blockDim.x;
    const int gtid = blockIdx.x * blockDim.x + threadIdx.x;
    if (gtid >= n4) return;

    int k = (n4 - 1 - gtid) / S;  // highest valid stride index for this thread

    for (; k >= 3; k -= 4) {
        int i0 = gtid + k * S;
        int i1 = i0 - S;
        int i2 = i0 - 2 * S;
        int i3 = i0 - 3 * S;
        float4 a = __ldcs(&x4[i0]);
        float4 b = __ldcs(&x4[i1]);
        float4 c = __ldcs(&x4[i2]);
        float4 d = __ldcs(&x4[i3]);
        __stcs(&out4[i0], fq4(a, mn, scale, inv));
        __stcs(&out4[i1], fq4(b, mn, scale, inv));
        __stcs(&out4[i2], fq4(c, mn, scale, inv));
        __stcs(&out4[i3], fq4(d, mn, scale, inv));
    }
    for (; k >= 0; --k) {
        int i0 = gtid + k * S;
        __stcs(&out4[i0], fq4(__ldcs(&x4[i0]), mn, scale, inv));
    }
}

// Scalar tail (never hit for this shape: n % 1024 == 0; kept for generality).
__global__ void fakequant_tail_kernel(const float* __restrict__ x,
                                      float* __restrict__ out,
                                      int start, int n) {
    float mn = 3.402823466e+38f;
    float mx = -3.402823466e+38f;
    for (int p = 0; p < RED_BLOCKS; ++p) {
        float2 v = g_partials[p];
        mn = fminf(mn, v.x);
        mx = fmaxf(mx, v.y);
    }
    const float scale = 255.0f / (mx - mn);
    const float inv   = 1.0f / scale;
    int i = start + blockIdx.x * blockDim.x + threadIdx.x;
    if (i < n) out[i] = fmaf(rintf((x[i] - mn) * scale), inv, mn);
}

extern "C" void kernel_launch(void* const* d_in, const int* in_sizes, int n_in,
                              void* d_out, int out_size) {
    const float* x = (const float*)d_in[0];
    float* out = (float*)d_out;
    int n = in_sizes[0];
    int n4 = n >> 2;
    int tail_start = n4 << 2;

    // Keep the last ~112 MB of x L2-resident (L2 is ~126 MB).
    const long long KEEP_BYTES = 112LL * 1024 * 1024;
    int keep_elems = (int)(KEEP_BYTES / 16);  // float4s
    int keep_thresh = n4 > keep_elems ? n4 - keep_elems : 0;

    minmax_reduce_kernel<<<RED_BLOCKS, TPB>>>((const float4*)x, n4, keep_thresh);
    fakequant_apply_kernel<<<RED_BLOCKS, TPB>>>((const float4*)x, (float4*)out, n4);

    if (tail_start < n) {
        int tail = n - tail_start;
        fakequant_tail_kernel<<<(tail + TPB - 1) / TPB, TPB>>>(x, out, tail_start, n);
    }
}